// round 1
// baseline (speedup 1.0000x reference)
#include <cuda_runtime.h>
#include <math.h>

#define MAXN 131072
#define TPB 256

// ---------------- device scratch (static: no allocation allowed) ----------------
__device__ float  g_S[MAXN * 16];   // scatter accumulator (raw edge features)
__device__ float  g_deg[MAXN];      // degree accumulator
__device__ float  g_u[MAXN * 16];   // node features after Wp, pre node-BN
__device__ double g_est[32];        // edge BN stats: [0:16) sum, [16:32) sumsq
__device__ double g_nst[32];        // node BN stats
__device__ float  g_eac[32];        // edge BN affine: [0:16) a, [16:32) c
__device__ float  g_nac[32];        // node BN affine
__device__ int    g_idx64;          // 1 if edge_index is int64, 0 if int32

// ---------------- helpers ----------------
__device__ __forceinline__ float gelu_exact(float x) {
    // gelu(x) = 0.5*x*(1+erf(x/sqrt(2)))
    return 0.5f * x * (1.0f + erff(x * 0.70710678118654752440f));
}

__device__ __forceinline__ float warp_sum(float v) {
#pragma unroll
    for (int o = 16; o > 0; o >>= 1) v += __shfl_down_sync(0xffffffffu, v, o);
    return v;
}

// ---------------- kernels ----------------
__global__ void zero_kernel(int N) {
    int tid = blockIdx.x * blockDim.x + threadIdx.x;
    int tot = N * 16;
    if (tid < tot) g_S[tid] = 0.0f;
    if (tid < N)   g_deg[tid] = 0.0f;
    if (tid < 32) { g_est[tid] = 0.0; g_nst[tid] = 0.0; }
}

// Detect whether edge_index buffer is int64 or int32.
// If data is int32, interpreting pairs as int64 yields values with a random
// nonzero high word (node index in [0,N)) -> huge -> fails range check.
__global__ void probe_kernel(const void* __restrict__ eidx, int N) {
    if (threadIdx.x == 0 && blockIdx.x == 0) {
        const long long* q = (const long long*)eidx;
        int ok = 1;
#pragma unroll 1
        for (int i = 0; i < 64; i++) {
            long long v = q[i];
            if (v < 0 || v >= (long long)N) ok = 0;
        }
        g_idx64 = ok;
    }
}

__global__ __launch_bounds__(TPB) void edge_kernel(
    const float* __restrict__ coords, const float* __restrict__ normals,
    const float* __restrict__ curv, const void* __restrict__ eidx,
    long long E, int N,
    const float* __restrict__ W1, const float* __restrict__ b1,
    const float* __restrict__ W2, const float* __restrict__ b2,
    const float* __restrict__ W3, const float* __restrict__ b3)
{
    __shared__ float W1s[8 * 64];
    __shared__ float b1s[64];
    __shared__ float W2s[64 * 32];
    __shared__ float b2s[32];
    __shared__ float W3s[32 * 16];
    __shared__ float b3s[16];
    __shared__ float sred[32];

    for (int i = threadIdx.x; i < 512;  i += TPB) W1s[i] = W1[i];
    for (int i = threadIdx.x; i < 64;   i += TPB) b1s[i] = b1[i];
    for (int i = threadIdx.x; i < 2048; i += TPB) W2s[i] = W2[i];
    for (int i = threadIdx.x; i < 32;   i += TPB) b2s[i] = b2[i];
    for (int i = threadIdx.x; i < 512;  i += TPB) W3s[i] = W3[i];
    for (int i = threadIdx.x; i < 16;   i += TPB) b3s[i] = b3[i];
    if (threadIdx.x < 32) sred[threadIdx.x] = 0.0f;
    __syncthreads();

    const int use64 = g_idx64;
    const int*       e32 = (const int*)eidx;
    const long long* e64 = (const long long*)eidx;

    float s0[16], s1[16];
#pragma unroll
    for (int i = 0; i < 16; i++) { s0[i] = 0.0f; s1[i] = 0.0f; }

    const long long stride = (long long)gridDim.x * blockDim.x;
    for (long long e = (long long)blockIdx.x * blockDim.x + threadIdx.x; e < E; e += stride) {
        int r, c;
        if (use64) { r = (int)e64[e]; c = (int)e64[E + e]; }
        else       { r = e32[e];      c = e32[E + e]; }

        // --- geometric features ---
        float prx = coords[3 * r + 0], pry = coords[3 * r + 1], prz = coords[3 * r + 2];
        float pcx = coords[3 * c + 0], pcy = coords[3 * c + 1], pcz = coords[3 * c + 2];
        float dx = pcx - prx, dy = pcy - pry, dz = pcz - prz;

        float nrx = normals[3 * r + 0], nry = normals[3 * r + 1], nrz = normals[3 * r + 2];
        float ncx = normals[3 * c + 0], ncy = normals[3 * c + 1], ncz = normals[3 * c + 2];

        float ndot = nrx * ncx + nry * ncy + nrz * ncz;
        float dn = sqrtf(dx * dx + dy * dy + dz * dz) + 1e-8f;
        float invd = 1.0f / dn;
        float lo = -1.0f + 1e-8f, hi = 1.0f - 1e-8f;
        float cr = fminf(fmaxf((nrx * dx + nry * dy + nrz * dz) * invd, lo), hi);
        float cc = fminf(fmaxf((ncx * dx + ncy * dy + ncz * dz) * invd, lo), hi);
        float cd0 = curv[4 * c + 0] - curv[4 * r + 0];
        float cd1 = curv[4 * c + 1] - curv[4 * r + 1];

        float f[8] = { dx, dy, dz, ndot, cr, cc, cd0, cd1 };

        // --- MLP layer 1+2 fused: h2 += gelu(f@W1+b1)[j] * W2[j,:] ---
        float h2[32];
#pragma unroll
        for (int i = 0; i < 32; i++) h2[i] = b2s[i];
#pragma unroll 4
        for (int j = 0; j < 64; j++) {
            float a = b1s[j];
#pragma unroll
            for (int k = 0; k < 8; k++) a = fmaf(f[k], W1s[k * 64 + j], a);
            a = gelu_exact(a);
#pragma unroll
            for (int i = 0; i < 32; i++) h2[i] = fmaf(a, W2s[j * 32 + i], h2[i]);
        }

        // --- layer 3 ---
        float ef[16];
#pragma unroll
        for (int i = 0; i < 16; i++) ef[i] = b3s[i];
#pragma unroll 4
        for (int j = 0; j < 32; j++) {
            float g = gelu_exact(h2[j]);
#pragma unroll
            for (int i = 0; i < 16; i++) ef[i] = fmaf(g, W3s[j * 16 + i], ef[i]);
        }

        // --- scatter raw ef to both endpoints (BN applied later: affine commutes
        // with the linear scatter: sum(a*ef+c) = a*sum(ef) + deg*c) ---
        float* Sr = &g_S[(size_t)r * 16];
        float* Sc = &g_S[(size_t)c * 16];
#pragma unroll
        for (int i = 0; i < 16; i++) {
            atomicAdd(Sr + i, ef[i]);
            atomicAdd(Sc + i, ef[i]);
        }
        atomicAdd(&g_deg[r], 1.0f);
        atomicAdd(&g_deg[c], 1.0f);

        // --- BN stats ---
#pragma unroll
        for (int i = 0; i < 16; i++) {
            s0[i] += ef[i];
            s1[i] = fmaf(ef[i], ef[i], s1[i]);
        }
    }

    // reduce stats: warp -> shared -> global(double)
    int lane = threadIdx.x & 31;
#pragma unroll
    for (int i = 0; i < 16; i++) {
        float a = warp_sum(s0[i]);
        float b = warp_sum(s1[i]);
        if (lane == 0) {
            atomicAdd(&sred[i], a);
            atomicAdd(&sred[16 + i], b);
        }
    }
    __syncthreads();
    if (threadIdx.x < 32) atomicAdd(&g_est[threadIdx.x], (double)sred[threadIdx.x]);
}

__global__ void fin_edge_kernel(const float* __restrict__ gamma,
                                const float* __restrict__ beta, long long E) {
    int i = threadIdx.x;
    if (i < 16) {
        double invE = 1.0 / (double)E;
        double mean = g_est[i] * invE;
        double var = g_est[16 + i] * invE - mean * mean;
        if (var < 0.0) var = 0.0;
        float a = gamma[i] * rsqrtf((float)var + 1e-5f);
        g_eac[i] = a;
        g_eac[16 + i] = beta[i] - (float)mean * a;
    }
}

__global__ __launch_bounds__(TPB) void node_kernel(
    const float* __restrict__ Wp, const float* __restrict__ bp, int N)
{
    __shared__ float Wps[256];
    __shared__ float bps[16];
    __shared__ float sred[32];
    if (threadIdx.x < 256) Wps[threadIdx.x] = Wp[threadIdx.x];
    if (threadIdx.x < 16)  bps[threadIdx.x] = bp[threadIdx.x];
    if (threadIdx.x < 32)  sred[threadIdx.x] = 0.0f;
    __syncthreads();

    int n = blockIdx.x * blockDim.x + threadIdx.x;
    float s0[16], s1[16];
#pragma unroll
    for (int i = 0; i < 16; i++) { s0[i] = 0.0f; s1[i] = 0.0f; }

    if (n < N) {
        float deg = g_deg[n];
        float invd = 1.0f / fmaxf(deg, 1.0f);
        float t[16];
#pragma unroll
        for (int i = 0; i < 16; i++)
            t[i] = (g_eac[i] * g_S[(size_t)n * 16 + i] + deg * g_eac[16 + i]) * invd;
        float u[16];
#pragma unroll
        for (int i = 0; i < 16; i++) u[i] = bps[i];
#pragma unroll
        for (int j = 0; j < 16; j++) {
#pragma unroll
            for (int i = 0; i < 16; i++) u[i] = fmaf(t[j], Wps[j * 16 + i], u[i]);
        }
#pragma unroll
        for (int i = 0; i < 16; i++) {
            g_u[(size_t)n * 16 + i] = u[i];
            s0[i] = u[i];
            s1[i] = u[i] * u[i];
        }
    }

    int lane = threadIdx.x & 31;
#pragma unroll
    for (int i = 0; i < 16; i++) {
        float a = warp_sum(s0[i]);
        float b = warp_sum(s1[i]);
        if (lane == 0) {
            atomicAdd(&sred[i], a);
            atomicAdd(&sred[16 + i], b);
        }
    }
    __syncthreads();
    if (threadIdx.x < 32) atomicAdd(&g_nst[threadIdx.x], (double)sred[threadIdx.x]);
}

__global__ void fin_node_kernel(const float* __restrict__ gamma,
                                const float* __restrict__ beta, int N) {
    int i = threadIdx.x;
    if (i < 16) {
        double invN = 1.0 / (double)N;
        double mean = g_nst[i] * invN;
        double var = g_nst[16 + i] * invN - mean * mean;
        if (var < 0.0) var = 0.0;
        float a = gamma[i] * rsqrtf((float)var + 1e-5f);
        g_nac[i] = a;
        g_nac[16 + i] = beta[i] - (float)mean * a;
    }
}

__global__ void final_kernel(float* __restrict__ out, int N) {
    int idx4 = blockIdx.x * blockDim.x + threadIdx.x;   // float4 index
    int tot4 = N * 4;                                   // N*16/4
    if (idx4 < tot4) {
        int base = (idx4 * 4) & 15;                     // feature index of .x
        const float4* u4 = (const float4*)g_u;
        float4 v = u4[idx4];
        float4 r;
        r.x = g_nac[base + 0] * v.x + g_nac[16 + base + 0];
        r.y = g_nac[base + 1] * v.y + g_nac[16 + base + 1];
        r.z = g_nac[base + 2] * v.z + g_nac[16 + base + 2];
        r.w = g_nac[base + 3] * v.w + g_nac[16 + base + 3];
        ((float4*)out)[idx4] = r;
    }
}

// ---------------- launch ----------------
extern "C" void kernel_launch(void* const* d_in, const int* in_sizes, int n_in,
                              void* d_out, int out_size)
{
    const float* coords  = (const float*)d_in[0];
    const float* normals = (const float*)d_in[1];
    const float* curv    = (const float*)d_in[2];
    const void*  eidx    = d_in[3];
    const float* W1 = (const float*)d_in[4];
    const float* b1 = (const float*)d_in[5];
    const float* W2 = (const float*)d_in[6];
    const float* b2 = (const float*)d_in[7];
    const float* W3 = (const float*)d_in[8];
    const float* b3 = (const float*)d_in[9];
    const float* bn_e_gamma = (const float*)d_in[10];
    const float* bn_e_beta  = (const float*)d_in[11];
    const float* Wp = (const float*)d_in[12];
    const float* bp = (const float*)d_in[13];
    const float* bn_n_gamma = (const float*)d_in[14];
    const float* bn_n_beta  = (const float*)d_in[15];

    int N = in_sizes[0] / 3;
    long long E = (long long)(in_sizes[3] / 2);
    float* out = (float*)d_out;

    zero_kernel<<<(N * 16 + TPB - 1) / TPB, TPB>>>(N);
    probe_kernel<<<1, 32>>>(eidx, N);
    edge_kernel<<<1184, TPB>>>(coords, normals, curv, eidx, E, N,
                               W1, b1, W2, b2, W3, b3);
    fin_edge_kernel<<<1, 32>>>(bn_e_gamma, bn_e_beta, E);
    node_kernel<<<(N + TPB - 1) / TPB, TPB>>>(Wp, bp, N);
    fin_node_kernel<<<1, 32>>>(bn_n_gamma, bn_n_beta, N);
    final_kernel<<<(N * 4 + TPB - 1) / TPB, TPB>>>(out, N);
}

// round 2
// speedup vs baseline: 1.1030x; 1.1030x over previous
#include <cuda_runtime.h>
#include <math.h>

#define MAXN 131072
#define TPB 256

// ---------------- device scratch ----------------
__device__ __align__(256) float  g_S[MAXN * 16];
__device__ float  g_deg[MAXN];
__device__ __align__(256) float  g_u[MAXN * 16];
__device__ double g_est[32];
__device__ double g_nst[32];
__device__ float  g_eac[32];
__device__ float  g_nac[32];
__device__ int    g_idx64;

// ---------------- helpers ----------------
__device__ __forceinline__ float gelu_exact(float x) {
    return 0.5f * x * (1.0f + erff(x * 0.70710678118654752440f));
}

__device__ __forceinline__ float warp_sum(float v) {
#pragma unroll
    for (int o = 16; o > 0; o >>= 1) v += __shfl_down_sync(0xffffffffu, v, o);
    return v;
}

__device__ __forceinline__ void red_add_v4(float* addr, float a, float b, float c, float d) {
    asm volatile("red.global.add.v4.f32 [%0], {%1,%2,%3,%4};"
                 :: "l"(addr), "f"(a), "f"(b), "f"(c), "f"(d) : "memory");
}

// ---------------- kernels ----------------
__global__ void zero_kernel(int N) {
    int tid = blockIdx.x * blockDim.x + threadIdx.x;
    int tot = N * 16;
    if (tid < tot) g_S[tid] = 0.0f;
    if (tid < N)   g_deg[tid] = 0.0f;
    if (tid < 32) { g_est[tid] = 0.0; g_nst[tid] = 0.0; }
}

__global__ void probe_kernel(const void* __restrict__ eidx, int N) {
    if (threadIdx.x == 0 && blockIdx.x == 0) {
        const long long* q = (const long long*)eidx;
        int ok = 1;
#pragma unroll 1
        for (int i = 0; i < 64; i++) {
            long long v = q[i];
            if (v < 0 || v >= (long long)N) ok = 0;
        }
        g_idx64 = ok;
    }
}

__global__ void dummy_kernel() {}   // aligns edge_kernel to ncu launch index 5

__global__ __launch_bounds__(TPB) void edge_kernel(
    const float* __restrict__ coords, const float* __restrict__ normals,
    const float* __restrict__ curv, const void* __restrict__ eidx,
    long long E, int N,
    const float* __restrict__ W1, const float* __restrict__ b1,
    const float* __restrict__ W2, const float* __restrict__ b2,
    const float* __restrict__ W3, const float* __restrict__ b3)
{
    // All weights staged as float4-readable shared arrays.
    __shared__ float4 W1t4[64 * 2];   // transposed W1: row j holds 8 inputs
    __shared__ float  b1s[64];
    __shared__ float4 W2s4[64 * 8];   // row j: 32 outputs
    __shared__ float  b2s[32];
    __shared__ float4 W3s4[32 * 4];   // row j: 16 outputs
    __shared__ float  b3s[16];
    __shared__ float  sred[32];

    {
        float* W1t = (float*)W1t4;
        for (int i = threadIdx.x; i < 512; i += TPB) {
            int k = i >> 6, j = i & 63;            // W1[k,j]
            W1t[j * 8 + k] = W1[i];
        }
        float* W2f = (float*)W2s4;
        for (int i = threadIdx.x; i < 2048; i += TPB) W2f[i] = W2[i];
        float* W3f = (float*)W3s4;
        for (int i = threadIdx.x; i < 512;  i += TPB) W3f[i] = W3[i];
        for (int i = threadIdx.x; i < 64;   i += TPB) b1s[i] = b1[i];
        for (int i = threadIdx.x; i < 32;   i += TPB) b2s[i] = b2[i];
        for (int i = threadIdx.x; i < 16;   i += TPB) b3s[i] = b3[i];
        if (threadIdx.x < 32) sred[threadIdx.x] = 0.0f;
    }
    __syncthreads();

    const int use64 = g_idx64;
    const int*       e32 = (const int*)eidx;
    const long long* e64 = (const long long*)eidx;

    float s0[16], s1[16];
#pragma unroll
    for (int i = 0; i < 16; i++) { s0[i] = 0.0f; s1[i] = 0.0f; }

    const long long stride = (long long)gridDim.x * blockDim.x;
    for (long long e = (long long)blockIdx.x * blockDim.x + threadIdx.x; e < E; e += stride) {
        int r, c;
        if (use64) { r = (int)e64[e]; c = (int)e64[E + e]; }
        else       { r = e32[e];      c = e32[E + e]; }

        float prx = coords[3 * r + 0], pry = coords[3 * r + 1], prz = coords[3 * r + 2];
        float pcx = coords[3 * c + 0], pcy = coords[3 * c + 1], pcz = coords[3 * c + 2];
        float dx = pcx - prx, dy = pcy - pry, dz = pcz - prz;

        float nrx = normals[3 * r + 0], nry = normals[3 * r + 1], nrz = normals[3 * r + 2];
        float ncx = normals[3 * c + 0], ncy = normals[3 * c + 1], ncz = normals[3 * c + 2];

        float ndot = nrx * ncx + nry * ncy + nrz * ncz;
        float dn = sqrtf(dx * dx + dy * dy + dz * dz) + 1e-8f;
        float invd = 1.0f / dn;
        float lo = -1.0f + 1e-8f, hi = 1.0f - 1e-8f;
        float cr = fminf(fmaxf((nrx * dx + nry * dy + nrz * dz) * invd, lo), hi);
        float cc = fminf(fmaxf((ncx * dx + ncy * dy + ncz * dz) * invd, lo), hi);
        const float2* cv = (const float2*)curv;
        float2 cvr = cv[2 * r], cvc = cv[2 * c];
        float cd0 = cvc.x - cvr.x;
        float cd1 = cvc.y - cvr.y;

        // --- layers 1+2 fused ---
        float h2[32];
#pragma unroll
        for (int i = 0; i < 32; i++) h2[i] = b2s[i];
#pragma unroll 4
        for (int j = 0; j < 64; j++) {
            float4 wa = W1t4[2 * j], wb = W1t4[2 * j + 1];
            float a = b1s[j];
            a = fmaf(dx, wa.x, a);  a = fmaf(dy, wa.y, a);
            a = fmaf(dz, wa.z, a);  a = fmaf(ndot, wa.w, a);
            a = fmaf(cr, wb.x, a);  a = fmaf(cc, wb.y, a);
            a = fmaf(cd0, wb.z, a); a = fmaf(cd1, wb.w, a);
            a = gelu_exact(a);
            const float4* w = &W2s4[j * 8];
#pragma unroll
            for (int q = 0; q < 8; q++) {
                float4 wv = w[q];
                h2[4 * q + 0] = fmaf(a, wv.x, h2[4 * q + 0]);
                h2[4 * q + 1] = fmaf(a, wv.y, h2[4 * q + 1]);
                h2[4 * q + 2] = fmaf(a, wv.z, h2[4 * q + 2]);
                h2[4 * q + 3] = fmaf(a, wv.w, h2[4 * q + 3]);
            }
        }

        // --- layer 3 ---
        float ef[16];
#pragma unroll
        for (int i = 0; i < 16; i++) ef[i] = b3s[i];
#pragma unroll 4
        for (int j = 0; j < 32; j++) {
            float g = gelu_exact(h2[j]);
            const float4* w = &W3s4[j * 4];
#pragma unroll
            for (int q = 0; q < 4; q++) {
                float4 wv = w[q];
                ef[4 * q + 0] = fmaf(g, wv.x, ef[4 * q + 0]);
                ef[4 * q + 1] = fmaf(g, wv.y, ef[4 * q + 1]);
                ef[4 * q + 2] = fmaf(g, wv.z, ef[4 * q + 2]);
                ef[4 * q + 3] = fmaf(g, wv.w, ef[4 * q + 3]);
            }
        }

        // --- vectorized scatter (raw ef; BN affine applied at node stage) ---
        float* Sr = &g_S[(size_t)r * 16];
        float* Sc = &g_S[(size_t)c * 16];
#pragma unroll
        for (int q = 0; q < 4; q++) {
            red_add_v4(Sr + 4 * q, ef[4 * q], ef[4 * q + 1], ef[4 * q + 2], ef[4 * q + 3]);
            red_add_v4(Sc + 4 * q, ef[4 * q], ef[4 * q + 1], ef[4 * q + 2], ef[4 * q + 3]);
        }
        atomicAdd(&g_deg[r], 1.0f);
        atomicAdd(&g_deg[c], 1.0f);

        // --- BN stats ---
#pragma unroll
        for (int i = 0; i < 16; i++) {
            s0[i] += ef[i];
            s1[i] = fmaf(ef[i], ef[i], s1[i]);
        }
    }

    int lane = threadIdx.x & 31;
#pragma unroll
    for (int i = 0; i < 16; i++) {
        float a = warp_sum(s0[i]);
        float b = warp_sum(s1[i]);
        if (lane == 0) {
            atomicAdd(&sred[i], a);
            atomicAdd(&sred[16 + i], b);
        }
    }
    __syncthreads();
    if (threadIdx.x < 32) atomicAdd(&g_est[threadIdx.x], (double)sred[threadIdx.x]);
}

__global__ void fin_edge_kernel(const float* __restrict__ gamma,
                                const float* __restrict__ beta, long long E) {
    int i = threadIdx.x;
    if (i < 16) {
        double invE = 1.0 / (double)E;
        double mean = g_est[i] * invE;
        double var = g_est[16 + i] * invE - mean * mean;
        if (var < 0.0) var = 0.0;
        float a = gamma[i] * rsqrtf((float)var + 1e-5f);
        g_eac[i] = a;
        g_eac[16 + i] = beta[i] - (float)mean * a;
    }
}

__global__ __launch_bounds__(TPB) void node_kernel(
    const float* __restrict__ Wp, const float* __restrict__ bp, int N)
{
    __shared__ float Wps[256];
    __shared__ float bps[16];
    __shared__ float sred[32];
    if (threadIdx.x < 256) Wps[threadIdx.x] = Wp[threadIdx.x];
    if (threadIdx.x < 16)  bps[threadIdx.x] = bp[threadIdx.x];
    if (threadIdx.x < 32)  sred[threadIdx.x] = 0.0f;
    __syncthreads();

    int n = blockIdx.x * blockDim.x + threadIdx.x;
    float s0[16], s1[16];
#pragma unroll
    for (int i = 0; i < 16; i++) { s0[i] = 0.0f; s1[i] = 0.0f; }

    if (n < N) {
        float deg = g_deg[n];
        float invd = 1.0f / fmaxf(deg, 1.0f);
        float t[16];
#pragma unroll
        for (int i = 0; i < 16; i++)
            t[i] = (g_eac[i] * g_S[(size_t)n * 16 + i] + deg * g_eac[16 + i]) * invd;
        float u[16];
#pragma unroll
        for (int i = 0; i < 16; i++) u[i] = bps[i];
#pragma unroll
        for (int j = 0; j < 16; j++) {
#pragma unroll
            for (int i = 0; i < 16; i++) u[i] = fmaf(t[j], Wps[j * 16 + i], u[i]);
        }
#pragma unroll
        for (int i = 0; i < 16; i++) {
            g_u[(size_t)n * 16 + i] = u[i];
            s0[i] = u[i];
            s1[i] = u[i] * u[i];
        }
    }

    int lane = threadIdx.x & 31;
#pragma unroll
    for (int i = 0; i < 16; i++) {
        float a = warp_sum(s0[i]);
        float b = warp_sum(s1[i]);
        if (lane == 0) {
            atomicAdd(&sred[i], a);
            atomicAdd(&sred[16 + i], b);
        }
    }
    __syncthreads();
    if (threadIdx.x < 32) atomicAdd(&g_nst[threadIdx.x], (double)sred[threadIdx.x]);
}

__global__ void fin_node_kernel(const float* __restrict__ gamma,
                                const float* __restrict__ beta, int N) {
    int i = threadIdx.x;
    if (i < 16) {
        double invN = 1.0 / (double)N;
        double mean = g_nst[i] * invN;
        double var = g_nst[16 + i] * invN - mean * mean;
        if (var < 0.0) var = 0.0;
        float a = gamma[i] * rsqrtf((float)var + 1e-5f);
        g_nac[i] = a;
        g_nac[16 + i] = beta[i] - (float)mean * a;
    }
}

__global__ void final_kernel(float* __restrict__ out, int N) {
    int idx4 = blockIdx.x * blockDim.x + threadIdx.x;
    int tot4 = N * 4;
    if (idx4 < tot4) {
        int base = (idx4 * 4) & 15;
        const float4* u4 = (const float4*)g_u;
        float4 v = u4[idx4];
        float4 r;
        r.x = g_nac[base + 0] * v.x + g_nac[16 + base + 0];
        r.y = g_nac[base + 1] * v.y + g_nac[16 + base + 1];
        r.z = g_nac[base + 2] * v.z + g_nac[16 + base + 2];
        r.w = g_nac[base + 3] * v.w + g_nac[16 + base + 3];
        ((float4*)out)[idx4] = r;
    }
}

// ---------------- launch ----------------
extern "C" void kernel_launch(void* const* d_in, const int* in_sizes, int n_in,
                              void* d_out, int out_size)
{
    const float* coords  = (const float*)d_in[0];
    const float* normals = (const float*)d_in[1];
    const float* curv    = (const float*)d_in[2];
    const void*  eidx    = d_in[3];
    const float* W1 = (const float*)d_in[4];
    const float* b1 = (const float*)d_in[5];
    const float* W2 = (const float*)d_in[6];
    const float* b2 = (const float*)d_in[7];
    const float* W3 = (const float*)d_in[8];
    const float* b3 = (const float*)d_in[9];
    const float* bn_e_gamma = (const float*)d_in[10];
    const float* bn_e_beta  = (const float*)d_in[11];
    const float* Wp = (const float*)d_in[12];
    const float* bp = (const float*)d_in[13];
    const float* bn_n_gamma = (const float*)d_in[14];
    const float* bn_n_beta  = (const float*)d_in[15];

    int N = in_sizes[0] / 3;
    long long E = (long long)(in_sizes[3] / 2);
    float* out = (float*)d_out;

    zero_kernel<<<(N * 16 + TPB - 1) / TPB, TPB>>>(N);
    probe_kernel<<<1, 32>>>(eidx, N);
    dummy_kernel<<<1, 32>>>();
    edge_kernel<<<1184, TPB>>>(coords, normals, curv, eidx, E, N,
                               W1, b1, W2, b2, W3, b3);
    fin_edge_kernel<<<1, 32>>>(bn_e_gamma, bn_e_beta, E);
    node_kernel<<<(N + TPB - 1) / TPB, TPB>>>(Wp, bp, N);
    fin_node_kernel<<<1, 32>>>(bn_n_gamma, bn_n_beta, N);
    final_kernel<<<(N * 4 + TPB - 1) / TPB, TPB>>>(out, N);
}

// round 3
// speedup vs baseline: 3.3085x; 2.9996x over previous
#include <cuda_runtime.h>
#include <math.h>

#define MAXN 131072
#define TPB 256
#define ETPB 128

// ---------------- device scratch ----------------
__device__ __align__(256) float  g_S[MAXN * 16];
__device__ float  g_deg[MAXN];
__device__ __align__(256) float  g_u[MAXN * 16];
__device__ __align__(256) float4 g_nA[MAXN];   // coords.xyz, curv0
__device__ __align__(256) float4 g_nB[MAXN];   // normals.xyz, curv1
__device__ double g_est[32];   // [0:16) 0.5*sum(S) (=sum ef), [16:32) sum ef^2
__device__ double g_nst[32];
__device__ float  g_eac[32];
__device__ float  g_nac[32];
__device__ int    g_idx64;

// ---------------- helpers ----------------
__device__ __forceinline__ float gelu_exact(float x) {
    return 0.5f * x * (1.0f + erff(x * 0.70710678118654752440f));
}
__device__ __forceinline__ float warp_sum(float v) {
#pragma unroll
    for (int o = 16; o > 0; o >>= 1) v += __shfl_down_sync(0xffffffffu, v, o);
    return v;
}
__device__ __forceinline__ void red_add_v4(float* addr, float a, float b, float c, float d) {
    asm volatile("red.global.add.v4.f32 [%0], {%1,%2,%3,%4};"
                 :: "l"(addr), "f"(a), "f"(b), "f"(c), "f"(d) : "memory");
}

// ---------------- kernels ----------------
__global__ void zero_kernel(int N) {
    int tid = blockIdx.x * blockDim.x + threadIdx.x;
    int tot = N * 16;
    if (tid < tot) g_S[tid] = 0.0f;
    if (tid < N)   g_deg[tid] = 0.0f;
    if (tid < 32) { g_est[tid] = 0.0; g_nst[tid] = 0.0; }
}

__global__ void probe_kernel(const void* __restrict__ eidx, int N) {
    if (threadIdx.x == 0 && blockIdx.x == 0) {
        const long long* q = (const long long*)eidx;
        int ok = 1;
#pragma unroll 1
        for (int i = 0; i < 64; i++) {
            long long v = q[i];
            if (v < 0 || v >= (long long)N) ok = 0;
        }
        g_idx64 = ok;
    }
}

__global__ void pack_kernel(const float* __restrict__ coords,
                            const float* __restrict__ normals,
                            const float* __restrict__ curv, int N) {
    int n = blockIdx.x * blockDim.x + threadIdx.x;
    if (n < N) {
        g_nA[n] = make_float4(coords[3*n], coords[3*n+1], coords[3*n+2], curv[4*n]);
        g_nB[n] = make_float4(normals[3*n], normals[3*n+1], normals[3*n+2], curv[4*n+1]);
    }
}

__device__ __forceinline__ void edge_features(
    const float4& Ar, const float4& Br, const float4& Ac, const float4& Bc, float* f)
{
    float dx = Ac.x - Ar.x, dy = Ac.y - Ar.y, dz = Ac.z - Ar.z;
    float ndot = Br.x * Bc.x + Br.y * Bc.y + Br.z * Bc.z;
    float dn = sqrtf(dx*dx + dy*dy + dz*dz) + 1e-8f;
    float invd = 1.0f / dn;
    float lo = -1.0f + 1e-8f, hi = 1.0f - 1e-8f;
    float cr = fminf(fmaxf((Br.x*dx + Br.y*dy + Br.z*dz) * invd, lo), hi);
    float cc = fminf(fmaxf((Bc.x*dx + Bc.y*dy + Bc.z*dz) * invd, lo), hi);
    f[0]=dx; f[1]=dy; f[2]=dz; f[3]=ndot; f[4]=cr; f[5]=cc;
    f[6]=Ac.w - Ar.w; f[7]=Bc.w - Br.w;
}

__global__ __launch_bounds__(ETPB) void edge_kernel(
    const void* __restrict__ eidx, long long E,
    const float* __restrict__ W1, const float* __restrict__ b1,
    const float* __restrict__ W2, const float* __restrict__ b2,
    const float* __restrict__ W3, const float* __restrict__ b3)
{
    __shared__ float4 W1t4[64 * 2];
    __shared__ float  b1s[64];
    __shared__ float4 W2s4[64 * 8];
    __shared__ float  b2s[32];
    __shared__ float4 W3s4[32 * 4];
    __shared__ float  b3s[16];
    __shared__ float  sred[16];

    {
        float* W1t = (float*)W1t4;
        for (int i = threadIdx.x; i < 512; i += ETPB) {
            int k = i >> 6, j = i & 63;
            W1t[j * 8 + k] = W1[i];
        }
        float* W2f = (float*)W2s4;
        for (int i = threadIdx.x; i < 2048; i += ETPB) W2f[i] = W2[i];
        float* W3f = (float*)W3s4;
        for (int i = threadIdx.x; i < 512;  i += ETPB) W3f[i] = W3[i];
        for (int i = threadIdx.x; i < 64;   i += ETPB) b1s[i] = b1[i];
        for (int i = threadIdx.x; i < 32;   i += ETPB) b2s[i] = b2[i];
        for (int i = threadIdx.x; i < 16;   i += ETPB) b3s[i] = b3[i];
        if (threadIdx.x < 16) sred[threadIdx.x] = 0.0f;
    }
    __syncthreads();

    const int use64 = g_idx64;
    const int*       e32 = (const int*)eidx;
    const long long* e64 = (const long long*)eidx;

    float s1[16];
#pragma unroll
    for (int i = 0; i < 16; i++) s1[i] = 0.0f;

    const long long stride = (long long)gridDim.x * ETPB * 2;
    for (long long e = ((long long)blockIdx.x * ETPB + threadIdx.x) * 2; e < E; e += stride) {
        bool dual = (e + 1 < E);
        long long e1 = dual ? e + 1 : e;
        int r0, c0, r1, c1;
        if (use64) {
            r0 = (int)e64[e];  c0 = (int)e64[E + e];
            r1 = (int)e64[e1]; c1 = (int)e64[E + e1];
        } else {
            r0 = e32[e];  c0 = e32[E + e];
            r1 = e32[e1]; c1 = e32[E + e1];
        }

        float4 Ar0 = __ldg(&g_nA[r0]), Br0 = __ldg(&g_nB[r0]);
        float4 Ac0 = __ldg(&g_nA[c0]), Bc0 = __ldg(&g_nB[c0]);
        float4 Ar1 = __ldg(&g_nA[r1]), Br1 = __ldg(&g_nB[r1]);
        float4 Ac1 = __ldg(&g_nA[c1]), Bc1 = __ldg(&g_nB[c1]);

        float f0[8], f1[8];
        edge_features(Ar0, Br0, Ac0, Bc0, f0);
        edge_features(Ar1, Br1, Ac1, Bc1, f1);

        // --- layers 1+2 fused, dual edge ---
        float h2a[32], h2b[32];
#pragma unroll
        for (int i = 0; i < 32; i++) { h2a[i] = b2s[i]; h2b[i] = b2s[i]; }
#pragma unroll 2
        for (int j = 0; j < 64; j++) {
            float4 wa = W1t4[2 * j], wb = W1t4[2 * j + 1];
            float bj = b1s[j];
            float a0 = bj, a1 = bj;
            a0 = fmaf(f0[0], wa.x, a0); a1 = fmaf(f1[0], wa.x, a1);
            a0 = fmaf(f0[1], wa.y, a0); a1 = fmaf(f1[1], wa.y, a1);
            a0 = fmaf(f0[2], wa.z, a0); a1 = fmaf(f1[2], wa.z, a1);
            a0 = fmaf(f0[3], wa.w, a0); a1 = fmaf(f1[3], wa.w, a1);
            a0 = fmaf(f0[4], wb.x, a0); a1 = fmaf(f1[4], wb.x, a1);
            a0 = fmaf(f0[5], wb.y, a0); a1 = fmaf(f1[5], wb.y, a1);
            a0 = fmaf(f0[6], wb.z, a0); a1 = fmaf(f1[6], wb.z, a1);
            a0 = fmaf(f0[7], wb.w, a0); a1 = fmaf(f1[7], wb.w, a1);
            a0 = gelu_exact(a0); a1 = gelu_exact(a1);
            const float4* w = &W2s4[j * 8];
#pragma unroll
            for (int q = 0; q < 8; q++) {
                float4 wv = w[q];
                h2a[4*q+0] = fmaf(a0, wv.x, h2a[4*q+0]); h2b[4*q+0] = fmaf(a1, wv.x, h2b[4*q+0]);
                h2a[4*q+1] = fmaf(a0, wv.y, h2a[4*q+1]); h2b[4*q+1] = fmaf(a1, wv.y, h2b[4*q+1]);
                h2a[4*q+2] = fmaf(a0, wv.z, h2a[4*q+2]); h2b[4*q+2] = fmaf(a1, wv.z, h2b[4*q+2]);
                h2a[4*q+3] = fmaf(a0, wv.w, h2a[4*q+3]); h2b[4*q+3] = fmaf(a1, wv.w, h2b[4*q+3]);
            }
        }

        // --- layer 3, dual edge ---
        float ef0[16], ef1[16];
#pragma unroll
        for (int i = 0; i < 16; i++) { ef0[i] = b3s[i]; ef1[i] = b3s[i]; }
#pragma unroll 2
        for (int j = 0; j < 32; j++) {
            float g0 = gelu_exact(h2a[j]);
            float g1 = gelu_exact(h2b[j]);
            const float4* w = &W3s4[j * 4];
#pragma unroll
            for (int q = 0; q < 4; q++) {
                float4 wv = w[q];
                ef0[4*q+0] = fmaf(g0, wv.x, ef0[4*q+0]); ef1[4*q+0] = fmaf(g1, wv.x, ef1[4*q+0]);
                ef0[4*q+1] = fmaf(g0, wv.y, ef0[4*q+1]); ef1[4*q+1] = fmaf(g1, wv.y, ef1[4*q+1]);
                ef0[4*q+2] = fmaf(g0, wv.z, ef0[4*q+2]); ef1[4*q+2] = fmaf(g1, wv.z, ef1[4*q+2]);
                ef0[4*q+3] = fmaf(g0, wv.w, ef0[4*q+3]); ef1[4*q+3] = fmaf(g1, wv.w, ef1[4*q+3]);
            }
        }

        // --- scatter ---
        float* Sr0 = &g_S[(size_t)r0 * 16];
        float* Sc0 = &g_S[(size_t)c0 * 16];
#pragma unroll
        for (int q = 0; q < 4; q++) {
            red_add_v4(Sr0 + 4*q, ef0[4*q], ef0[4*q+1], ef0[4*q+2], ef0[4*q+3]);
            red_add_v4(Sc0 + 4*q, ef0[4*q], ef0[4*q+1], ef0[4*q+2], ef0[4*q+3]);
        }
        atomicAdd(&g_deg[r0], 1.0f);
        atomicAdd(&g_deg[c0], 1.0f);
#pragma unroll
        for (int i = 0; i < 16; i++) s1[i] = fmaf(ef0[i], ef0[i], s1[i]);

        if (dual) {
            float* Sr1 = &g_S[(size_t)r1 * 16];
            float* Sc1 = &g_S[(size_t)c1 * 16];
#pragma unroll
            for (int q = 0; q < 4; q++) {
                red_add_v4(Sr1 + 4*q, ef1[4*q], ef1[4*q+1], ef1[4*q+2], ef1[4*q+3]);
                red_add_v4(Sc1 + 4*q, ef1[4*q], ef1[4*q+1], ef1[4*q+2], ef1[4*q+3]);
            }
            atomicAdd(&g_deg[r1], 1.0f);
            atomicAdd(&g_deg[c1], 1.0f);
#pragma unroll
            for (int i = 0; i < 16; i++) s1[i] = fmaf(ef1[i], ef1[i], s1[i]);
        }
    }

    int lane = threadIdx.x & 31;
#pragma unroll
    for (int i = 0; i < 16; i++) {
        float b = warp_sum(s1[i]);
        if (lane == 0) atomicAdd(&sred[i], b);
    }
    __syncthreads();
    if (threadIdx.x < 16) atomicAdd(&g_est[16 + threadIdx.x], (double)sred[threadIdx.x]);
}

// sum of g_S -> g_est[0:16) scaled by 0.5 (sum over edges of ef)
__global__ void sumS_kernel(int N) {
    float acc[4] = {0.f, 0.f, 0.f, 0.f};
    int tot4 = N * 4;
    int stride = gridDim.x * blockDim.x;          // 256*256: multiple of 4
    int t0 = blockIdx.x * blockDim.x + threadIdx.x;
    const float4* S4 = (const float4*)g_S;
    for (int i = t0; i < tot4; i += stride) {
        float4 v = S4[i];
        acc[0] += v.x; acc[1] += v.y; acc[2] += v.z; acc[3] += v.w;
    }
#pragma unroll
    for (int k = 0; k < 4; k++) {
#pragma unroll
        for (int o = 16; o >= 4; o >>= 1) acc[k] += __shfl_down_sync(0xffffffffu, acc[k], o);
    }
    int lane = threadIdx.x & 31;                  // lanes 0..3 hold class (t0&3)=lane
    if (lane < 4) {
        int base = ((t0 & 3)) * 4;                // == lane*4 since stride%4==0
#pragma unroll
        for (int k = 0; k < 4; k++)
            atomicAdd(&g_est[base + k], 0.5 * (double)acc[k]);
    }
}

__global__ void fin_edge_kernel(const float* __restrict__ gamma,
                                const float* __restrict__ beta, long long E) {
    int i = threadIdx.x;
    if (i < 16) {
        double invE = 1.0 / (double)E;
        double mean = g_est[i] * invE;
        double var = g_est[16 + i] * invE - mean * mean;
        if (var < 0.0) var = 0.0;
        float a = gamma[i] * rsqrtf((float)var + 1e-5f);
        g_eac[i] = a;
        g_eac[16 + i] = beta[i] - (float)mean * a;
    }
}

__global__ __launch_bounds__(TPB) void node_kernel(
    const float* __restrict__ Wp, const float* __restrict__ bp, int N)
{
    __shared__ float Wps[256];
    __shared__ float bps[16];
    __shared__ float sred[32];
    if (threadIdx.x < 256) Wps[threadIdx.x] = Wp[threadIdx.x];
    if (threadIdx.x < 16)  bps[threadIdx.x] = bp[threadIdx.x];
    if (threadIdx.x < 32)  sred[threadIdx.x] = 0.0f;
    __syncthreads();

    int n = blockIdx.x * blockDim.x + threadIdx.x;
    float s0[16], s1[16];
#pragma unroll
    for (int i = 0; i < 16; i++) { s0[i] = 0.0f; s1[i] = 0.0f; }

    if (n < N) {
        float deg = g_deg[n];
        float invd = 1.0f / fmaxf(deg, 1.0f);
        float t[16];
#pragma unroll
        for (int i = 0; i < 16; i++)
            t[i] = (g_eac[i] * g_S[(size_t)n * 16 + i] + deg * g_eac[16 + i]) * invd;
        float u[16];
#pragma unroll
        for (int i = 0; i < 16; i++) u[i] = bps[i];
#pragma unroll
        for (int j = 0; j < 16; j++) {
#pragma unroll
            for (int i = 0; i < 16; i++) u[i] = fmaf(t[j], Wps[j * 16 + i], u[i]);
        }
#pragma unroll
        for (int i = 0; i < 16; i++) {
            g_u[(size_t)n * 16 + i] = u[i];
            s0[i] = u[i];
            s1[i] = u[i] * u[i];
        }
    }

    int lane = threadIdx.x & 31;
#pragma unroll
    for (int i = 0; i < 16; i++) {
        float a = warp_sum(s0[i]);
        float b = warp_sum(s1[i]);
        if (lane == 0) {
            atomicAdd(&sred[i], a);
            atomicAdd(&sred[16 + i], b);
        }
    }
    __syncthreads();
    if (threadIdx.x < 32) atomicAdd(&g_nst[threadIdx.x], (double)sred[threadIdx.x]);
}

__global__ void fin_node_kernel(const float* __restrict__ gamma,
                                const float* __restrict__ beta, int N) {
    int i = threadIdx.x;
    if (i < 16) {
        double invN = 1.0 / (double)N;
        double mean = g_nst[i] * invN;
        double var = g_nst[16 + i] * invN - mean * mean;
        if (var < 0.0) var = 0.0;
        float a = gamma[i] * rsqrtf((float)var + 1e-5f);
        g_nac[i] = a;
        g_nac[16 + i] = beta[i] - (float)mean * a;
    }
}

__global__ void final_kernel(float* __restrict__ out, int N) {
    int idx4 = blockIdx.x * blockDim.x + threadIdx.x;
    int tot4 = N * 4;
    if (idx4 < tot4) {
        int base = (idx4 * 4) & 15;
        const float4* u4 = (const float4*)g_u;
        float4 v = u4[idx4];
        float4 r;
        r.x = g_nac[base + 0] * v.x + g_nac[16 + base + 0];
        r.y = g_nac[base + 1] * v.y + g_nac[16 + base + 1];
        r.z = g_nac[base + 2] * v.z + g_nac[16 + base + 2];
        r.w = g_nac[base + 3] * v.w + g_nac[16 + base + 3];
        ((float4*)out)[idx4] = r;
    }
}

// ---------------- launch ----------------
extern "C" void kernel_launch(void* const* d_in, const int* in_sizes, int n_in,
                              void* d_out, int out_size)
{
    const float* coords  = (const float*)d_in[0];
    const float* normals = (const float*)d_in[1];
    const float* curv    = (const float*)d_in[2];
    const void*  eidx    = d_in[3];
    const float* W1 = (const float*)d_in[4];
    const float* b1 = (const float*)d_in[5];
    const float* W2 = (const float*)d_in[6];
    const float* b2 = (const float*)d_in[7];
    const float* W3 = (const float*)d_in[8];
    const float* b3 = (const float*)d_in[9];
    const float* bn_e_gamma = (const float*)d_in[10];
    const float* bn_e_beta  = (const float*)d_in[11];
    const float* Wp = (const float*)d_in[12];
    const float* bp = (const float*)d_in[13];
    const float* bn_n_gamma = (const float*)d_in[14];
    const float* bn_n_beta  = (const float*)d_in[15];

    int N = in_sizes[0] / 3;
    long long E = (long long)(in_sizes[3] / 2);
    float* out = (float*)d_out;

    zero_kernel<<<(N * 16 + TPB - 1) / TPB, TPB>>>(N);          // 0
    probe_kernel<<<1, 32>>>(eidx, N);                            // 1
    pack_kernel<<<(N + TPB - 1) / TPB, TPB>>>(coords, normals, curv, N); // 2
    edge_kernel<<<1184, ETPB>>>(eidx, E, W1, b1, W2, b2, W3, b3);        // 3 (ncu slot)
    sumS_kernel<<<256, 256>>>(N);                                // 4
    fin_edge_kernel<<<1, 32>>>(bn_e_gamma, bn_e_beta, E);        // 5
    node_kernel<<<(N + TPB - 1) / TPB, TPB>>>(Wp, bp, N);        // 6
    fin_node_kernel<<<1, 32>>>(bn_n_gamma, bn_n_beta, N);        // 7
    final_kernel<<<(N * 4 + TPB - 1) / TPB, TPB>>>(out, N);      // 8
}

// round 4
// speedup vs baseline: 4.8599x; 1.4689x over previous
#include <cuda_runtime.h>
#include <math.h>

#define MAXN 131072
#define TPB 256
#define ETPB 128

typedef unsigned long long u64;

// ---------------- device scratch ----------------
__device__ __align__(256) float  g_S[MAXN * 16];
__device__ float  g_deg[MAXN];
__device__ __align__(256) float  g_u[MAXN * 16];
__device__ __align__(256) float4 g_nA[MAXN];   // coords.xyz, curv0
__device__ __align__(256) float4 g_nB[MAXN];   // normals.xyz, curv1
__device__ double g_est[32];
__device__ double g_nst[32];
__device__ float  g_eac[32];
__device__ float  g_nac[32];
__device__ int    g_idx64;

// ---------------- f32x2 helpers ----------------
__device__ __forceinline__ u64 pk2(float lo, float hi) {
    u64 r; asm("mov.b64 %0, {%1, %2};" : "=l"(r) : "f"(lo), "f"(hi)); return r;
}
__device__ __forceinline__ u64 dup2(float x) {
    u64 r; asm("mov.b64 %0, {%1, %1};" : "=l"(r) : "f"(x)); return r;
}
__device__ __forceinline__ void upk2(u64 a, float& lo, float& hi) {
    asm("mov.b64 {%0, %1}, %2;" : "=f"(lo), "=f"(hi) : "l"(a));
}
__device__ __forceinline__ u64 fma2(u64 a, u64 b, u64 c) {
    u64 d; asm("fma.rn.f32x2 %0, %1, %2, %3;" : "=l"(d) : "l"(a), "l"(b), "l"(c)); return d;
}
__device__ __forceinline__ u64 mul2(u64 a, u64 b) {
    u64 d; asm("mul.rn.f32x2 %0, %1, %2;" : "=l"(d) : "l"(a), "l"(b)); return d;
}
__device__ __forceinline__ float tanh_ap(float x) {
    float r; asm("tanh.approx.f32 %0, %1;" : "=f"(r) : "f"(x)); return r;
}
// packed tanh-form GELU: returns the 2 activations as scalars
__device__ __forceinline__ void gelu2(u64 x, u64 K1, u64 K3, float& o0, float& o1) {
    u64 p = mul2(x, x);
    u64 q = fma2(p, K3, K1);      // K1 + K3*x^2
    u64 u = mul2(x, q);           // x*(K1 + K3*x^2)
    float u0, u1; upk2(u, u0, u1);
    float t0 = tanh_ap(u0), t1 = tanh_ap(u1);
    float x0, x1; upk2(x, x0, x1);
    float h0 = 0.5f * x0, h1 = 0.5f * x1;
    o0 = fmaf(h0, t0, h0);
    o1 = fmaf(h1, t1, h1);
}

__device__ __forceinline__ float warp_sum(float v) {
#pragma unroll
    for (int o = 16; o > 0; o >>= 1) v += __shfl_down_sync(0xffffffffu, v, o);
    return v;
}
__device__ __forceinline__ void red_add_v4(float* addr, float a, float b, float c, float d) {
    asm volatile("red.global.add.v4.f32 [%0], {%1,%2,%3,%4};"
                 :: "l"(addr), "f"(a), "f"(b), "f"(c), "f"(d) : "memory");
}

// ---------------- kernels ----------------
__global__ void zero_kernel(int N) {
    int tid = blockIdx.x * blockDim.x + threadIdx.x;
    int tot = N * 16;
    if (tid < tot) g_S[tid] = 0.0f;
    if (tid < N)   g_deg[tid] = 0.0f;
    if (tid < 32) { g_est[tid] = 0.0; g_nst[tid] = 0.0; }
}

__global__ void probe_kernel(const void* __restrict__ eidx, int N) {
    if (threadIdx.x == 0 && blockIdx.x == 0) {
        const long long* q = (const long long*)eidx;
        int ok = 1;
#pragma unroll 1
        for (int i = 0; i < 64; i++) {
            long long v = q[i];
            if (v < 0 || v >= (long long)N) ok = 0;
        }
        g_idx64 = ok;
    }
}

__global__ void pack_kernel(const float* __restrict__ coords,
                            const float* __restrict__ normals,
                            const float* __restrict__ curv, int N) {
    int n = blockIdx.x * blockDim.x + threadIdx.x;
    if (n < N) {
        g_nA[n] = make_float4(coords[3*n], coords[3*n+1], coords[3*n+2], curv[4*n]);
        g_nB[n] = make_float4(normals[3*n], normals[3*n+1], normals[3*n+2], curv[4*n+1]);
    }
}

__device__ __forceinline__ void edge_features(
    const float4& Ar, const float4& Br, const float4& Ac, const float4& Bc, float* f)
{
    float dx = Ac.x - Ar.x, dy = Ac.y - Ar.y, dz = Ac.z - Ar.z;
    float ndot = Br.x * Bc.x + Br.y * Bc.y + Br.z * Bc.z;
    float dn = sqrtf(dx*dx + dy*dy + dz*dz) + 1e-8f;
    float invd = 1.0f / dn;
    float lo = -1.0f + 1e-8f, hi = 1.0f - 1e-8f;
    float cr = fminf(fmaxf((Br.x*dx + Br.y*dy + Br.z*dz) * invd, lo), hi);
    float cc = fminf(fmaxf((Bc.x*dx + Bc.y*dy + Bc.z*dz) * invd, lo), hi);
    f[0]=dx; f[1]=dy; f[2]=dz; f[3]=ndot; f[4]=cr; f[5]=cc;
    f[6]=Ac.w - Ar.w; f[7]=Bc.w - Br.w;
}

__global__ __launch_bounds__(ETPB) void edge_kernel(
    const void* __restrict__ eidx, long long E,
    const float* __restrict__ W1, const float* __restrict__ b1,
    const float* __restrict__ W2, const float* __restrict__ b2,
    const float* __restrict__ W3, const float* __restrict__ b3)
{
    // W1 interleaved into output-pair-major: entry (jp,k) = (W1[k][2jp], W1[k][2jp+1])
    __shared__ ulonglong2 W1p[32 * 4];   // [jp][kv], kv covers k=2kv,2kv+1
    __shared__ u64        b1p[32];
    __shared__ ulonglong2 W2p[64 * 8];   // natural row-major (adjacent outputs = pairs)
    __shared__ u64        b2p[16];
    __shared__ ulonglong2 W3p[32 * 4];   // natural row-major
    __shared__ u64        b3p[8];
    __shared__ float      sred[16];

    {
        float* w1f = (float*)W1p;
        for (int t = threadIdx.x; t < 512; t += ETPB) {
            int k = t >> 6, j = t & 63;         // reading W1[k][j]
            int jp = j >> 1, h = j & 1;
            w1f[(jp * 8 + k) * 2 + h] = W1[t];
        }
        float* w2f = (float*)W2p;
        for (int t = threadIdx.x; t < 2048; t += ETPB) w2f[t] = W2[t];
        float* w3f = (float*)W3p;
        for (int t = threadIdx.x; t < 512;  t += ETPB) w3f[t] = W3[t];
        float* b1f = (float*)b1p;
        for (int t = threadIdx.x; t < 64; t += ETPB) b1f[t] = b1[t];
        float* b2f = (float*)b2p;
        for (int t = threadIdx.x; t < 32; t += ETPB) b2f[t] = b2[t];
        float* b3f = (float*)b3p;
        for (int t = threadIdx.x; t < 16; t += ETPB) b3f[t] = b3[t];
        if (threadIdx.x < 16) sred[threadIdx.x] = 0.0f;
    }
    __syncthreads();

    const int use64 = g_idx64;
    const int*       e32 = (const int*)eidx;
    const long long* e64 = (const long long*)eidx;

    const u64 K1 = dup2(0.7978845608028654f);
    const u64 K3 = dup2(0.035677408136300125f);

    u64 s1p[8];
#pragma unroll
    for (int i = 0; i < 8; i++) s1p[i] = 0ull;

    const long long stride = (long long)gridDim.x * ETPB * 2;
    for (long long e = ((long long)blockIdx.x * ETPB + threadIdx.x) * 2; e < E; e += stride) {
        bool dual = (e + 1 < E);
        int r0, c0, r1, c1;
        if (use64) {
            if (dual) {
                longlong2 rr = *(const longlong2*)&e64[e];
                longlong2 cc2 = *(const longlong2*)&e64[E + e];
                r0 = (int)rr.x; r1 = (int)rr.y;
                c0 = (int)cc2.x; c1 = (int)cc2.y;
            } else {
                r0 = r1 = (int)e64[e]; c0 = c1 = (int)e64[E + e];
            }
        } else {
            r0 = e32[e];  c0 = e32[E + e];
            r1 = dual ? e32[e + 1] : r0;
            c1 = dual ? e32[E + e + 1] : c0;
        }

        float4 Ar0 = __ldg(&g_nA[r0]), Br0 = __ldg(&g_nB[r0]);
        float4 Ac0 = __ldg(&g_nA[c0]), Bc0 = __ldg(&g_nB[c0]);
        float4 Ar1 = __ldg(&g_nA[r1]), Br1 = __ldg(&g_nB[r1]);
        float4 Ac1 = __ldg(&g_nA[c1]), Bc1 = __ldg(&g_nB[c1]);

        float f0[8], f1[8];
        edge_features(Ar0, Br0, Ac0, Bc0, f0);
        edge_features(Ar1, Br1, Ac1, Bc1, f1);

        u64 fd0[8], fd1[8];
#pragma unroll
        for (int k = 0; k < 8; k++) { fd0[k] = dup2(f0[k]); fd1[k] = dup2(f1[k]); }

        // h2 accumulators: packed over adjacent outputs, per edge
        u64 h2a[16], h2b[16];
#pragma unroll
        for (int p = 0; p < 16; p++) { h2a[p] = b2p[p]; h2b[p] = h2a[p]; }

        // ---- L1 (packed over output pairs) -> gelu -> L2 rank-1 updates ----
#pragma unroll 2
        for (int jp = 0; jp < 32; jp++) {
            u64 acc0 = b1p[jp], acc1 = acc0;
#pragma unroll
            for (int kv = 0; kv < 4; kv++) {
                ulonglong2 w = W1p[jp * 4 + kv];
                acc0 = fma2(fd0[2*kv],   w.x, acc0);
                acc0 = fma2(fd0[2*kv+1], w.y, acc0);
                acc1 = fma2(fd1[2*kv],   w.x, acc1);
                acc1 = fma2(fd1[2*kv+1], w.y, acc1);
            }
            float a00, a01, a10, a11;
            gelu2(acc0, K1, K3, a00, a01);
            gelu2(acc1, K1, K3, a10, a11);
            u64 d00 = dup2(a00), d01 = dup2(a01);
            u64 d10 = dup2(a10), d11 = dup2(a11);
            // j = 2jp
            {
                const ulonglong2* w = &W2p[(2 * jp) * 8];
#pragma unroll
                for (int q = 0; q < 8; q++) {
                    ulonglong2 wv = w[q];
                    h2a[2*q]   = fma2(d00, wv.x, h2a[2*q]);
                    h2a[2*q+1] = fma2(d00, wv.y, h2a[2*q+1]);
                    h2b[2*q]   = fma2(d10, wv.x, h2b[2*q]);
                    h2b[2*q+1] = fma2(d10, wv.y, h2b[2*q+1]);
                }
            }
            // j = 2jp+1
            {
                const ulonglong2* w = &W2p[(2 * jp + 1) * 8];
#pragma unroll
                for (int q = 0; q < 8; q++) {
                    ulonglong2 wv = w[q];
                    h2a[2*q]   = fma2(d01, wv.x, h2a[2*q]);
                    h2a[2*q+1] = fma2(d01, wv.y, h2a[2*q+1]);
                    h2b[2*q]   = fma2(d11, wv.x, h2b[2*q]);
                    h2b[2*q+1] = fma2(d11, wv.y, h2b[2*q+1]);
                }
            }
        }

        // ---- gelu(h2) -> L3 ----
        u64 efa[8], efb[8];
#pragma unroll
        for (int p = 0; p < 8; p++) { efa[p] = b3p[p]; efb[p] = efa[p]; }
#pragma unroll 2
        for (int jp = 0; jp < 16; jp++) {
            float g00, g01, g10, g11;
            gelu2(h2a[jp], K1, K3, g00, g01);
            gelu2(h2b[jp], K1, K3, g10, g11);
            u64 d00 = dup2(g00), d01 = dup2(g01);
            u64 d10 = dup2(g10), d11 = dup2(g11);
            {
                const ulonglong2* w = &W3p[(2 * jp) * 4];
#pragma unroll
                for (int q = 0; q < 4; q++) {
                    ulonglong2 wv = w[q];
                    efa[2*q]   = fma2(d00, wv.x, efa[2*q]);
                    efa[2*q+1] = fma2(d00, wv.y, efa[2*q+1]);
                    efb[2*q]   = fma2(d10, wv.x, efb[2*q]);
                    efb[2*q+1] = fma2(d10, wv.y, efb[2*q+1]);
                }
            }
            {
                const ulonglong2* w = &W3p[(2 * jp + 1) * 4];
#pragma unroll
                for (int q = 0; q < 4; q++) {
                    ulonglong2 wv = w[q];
                    efa[2*q]   = fma2(d01, wv.x, efa[2*q]);
                    efa[2*q+1] = fma2(d01, wv.y, efa[2*q+1]);
                    efb[2*q]   = fma2(d11, wv.x, efb[2*q]);
                    efb[2*q+1] = fma2(d11, wv.y, efb[2*q+1]);
                }
            }
        }

        // ---- scatter + stats ----
        {
            float v[16];
#pragma unroll
            for (int p = 0; p < 8; p++) upk2(efa[p], v[2*p], v[2*p+1]);
            float* Sr = &g_S[(size_t)r0 * 16];
            float* Sc = &g_S[(size_t)c0 * 16];
#pragma unroll
            for (int q = 0; q < 4; q++) {
                red_add_v4(Sr + 4*q, v[4*q], v[4*q+1], v[4*q+2], v[4*q+3]);
                red_add_v4(Sc + 4*q, v[4*q], v[4*q+1], v[4*q+2], v[4*q+3]);
            }
            atomicAdd(&g_deg[r0], 1.0f);
            atomicAdd(&g_deg[c0], 1.0f);
#pragma unroll
            for (int p = 0; p < 8; p++) s1p[p] = fma2(efa[p], efa[p], s1p[p]);
        }
        if (dual) {
            float v[16];
#pragma unroll
            for (int p = 0; p < 8; p++) upk2(efb[p], v[2*p], v[2*p+1]);
            float* Sr = &g_S[(size_t)r1 * 16];
            float* Sc = &g_S[(size_t)c1 * 16];
#pragma unroll
            for (int q = 0; q < 4; q++) {
                red_add_v4(Sr + 4*q, v[4*q], v[4*q+1], v[4*q+2], v[4*q+3]);
                red_add_v4(Sc + 4*q, v[4*q], v[4*q+1], v[4*q+2], v[4*q+3]);
            }
            atomicAdd(&g_deg[r1], 1.0f);
            atomicAdd(&g_deg[c1], 1.0f);
#pragma unroll
            for (int p = 0; p < 8; p++) s1p[p] = fma2(efb[p], efb[p], s1p[p]);
        }
    }

    float s1[16];
#pragma unroll
    for (int p = 0; p < 8; p++) upk2(s1p[p], s1[2*p], s1[2*p+1]);
    int lane = threadIdx.x & 31;
#pragma unroll
    for (int i = 0; i < 16; i++) {
        float b = warp_sum(s1[i]);
        if (lane == 0) atomicAdd(&sred[i], b);
    }
    __syncthreads();
    if (threadIdx.x < 16) atomicAdd(&g_est[16 + threadIdx.x], (double)sred[threadIdx.x]);
}

// sum of g_S -> g_est[0:16) scaled by 0.5
__global__ void sumS_kernel(int N) {
    float acc[4] = {0.f, 0.f, 0.f, 0.f};
    int tot4 = N * 4;
    int stride = gridDim.x * blockDim.x;
    int t0 = blockIdx.x * blockDim.x + threadIdx.x;
    const float4* S4 = (const float4*)g_S;
    for (int i = t0; i < tot4; i += stride) {
        float4 v = S4[i];
        acc[0] += v.x; acc[1] += v.y; acc[2] += v.z; acc[3] += v.w;
    }
#pragma unroll
    for (int k = 0; k < 4; k++) {
#pragma unroll
        for (int o = 16; o >= 4; o >>= 1) acc[k] += __shfl_down_sync(0xffffffffu, acc[k], o);
    }
    int lane = threadIdx.x & 31;
    if (lane < 4) {
        int base = (t0 & 3) * 4;
#pragma unroll
        for (int k = 0; k < 4; k++)
            atomicAdd(&g_est[base + k], 0.5 * (double)acc[k]);
    }
}

__global__ void fin_edge_kernel(const float* __restrict__ gamma,
                                const float* __restrict__ beta, long long E) {
    int i = threadIdx.x;
    if (i < 16) {
        double invE = 1.0 / (double)E;
        double mean = g_est[i] * invE;
        double var = g_est[16 + i] * invE - mean * mean;
        if (var < 0.0) var = 0.0;
        float a = gamma[i] * rsqrtf((float)var + 1e-5f);
        g_eac[i] = a;
        g_eac[16 + i] = beta[i] - (float)mean * a;
    }
}

__global__ __launch_bounds__(TPB) void node_kernel(
    const float* __restrict__ Wp, const float* __restrict__ bp, int N)
{
    __shared__ float Wps[256];
    __shared__ float bps[16];
    __shared__ float sred[32];
    if (threadIdx.x < 256) Wps[threadIdx.x] = Wp[threadIdx.x];
    if (threadIdx.x < 16)  bps[threadIdx.x] = bp[threadIdx.x];
    if (threadIdx.x < 32)  sred[threadIdx.x] = 0.0f;
    __syncthreads();

    int n = blockIdx.x * blockDim.x + threadIdx.x;
    float s0[16], s1[16];
#pragma unroll
    for (int i = 0; i < 16; i++) { s0[i] = 0.0f; s1[i] = 0.0f; }

    if (n < N) {
        float deg = g_deg[n];
        float invd = 1.0f / fmaxf(deg, 1.0f);
        float t[16];
#pragma unroll
        for (int i = 0; i < 16; i++)
            t[i] = (g_eac[i] * g_S[(size_t)n * 16 + i] + deg * g_eac[16 + i]) * invd;
        float u[16];
#pragma unroll
        for (int i = 0; i < 16; i++) u[i] = bps[i];
#pragma unroll
        for (int j = 0; j < 16; j++) {
#pragma unroll
            for (int i = 0; i < 16; i++) u[i] = fmaf(t[j], Wps[j * 16 + i], u[i]);
        }
#pragma unroll
        for (int i = 0; i < 16; i++) {
            g_u[(size_t)n * 16 + i] = u[i];
            s0[i] = u[i];
            s1[i] = u[i] * u[i];
        }
    }

    int lane = threadIdx.x & 31;
#pragma unroll
    for (int i = 0; i < 16; i++) {
        float a = warp_sum(s0[i]);
        float b = warp_sum(s1[i]);
        if (lane == 0) {
            atomicAdd(&sred[i], a);
            atomicAdd(&sred[16 + i], b);
        }
    }
    __syncthreads();
    if (threadIdx.x < 32) atomicAdd(&g_nst[threadIdx.x], (double)sred[threadIdx.x]);
}

__global__ void fin_node_kernel(const float* __restrict__ gamma,
                                const float* __restrict__ beta, int N) {
    int i = threadIdx.x;
    if (i < 16) {
        double invN = 1.0 / (double)N;
        double mean = g_nst[i] * invN;
        double var = g_nst[16 + i] * invN - mean * mean;
        if (var < 0.0) var = 0.0;
        float a = gamma[i] * rsqrtf((float)var + 1e-5f);
        g_nac[i] = a;
        g_nac[16 + i] = beta[i] - (float)mean * a;
    }
}

__global__ void final_kernel(float* __restrict__ out, int N) {
    int idx4 = blockIdx.x * blockDim.x + threadIdx.x;
    int tot4 = N * 4;
    if (idx4 < tot4) {
        int base = (idx4 * 4) & 15;
        const float4* u4 = (const float4*)g_u;
        float4 v = u4[idx4];
        float4 r;
        r.x = g_nac[base + 0] * v.x + g_nac[16 + base + 0];
        r.y = g_nac[base + 1] * v.y + g_nac[16 + base + 1];
        r.z = g_nac[base + 2] * v.z + g_nac[16 + base + 2];
        r.w = g_nac[base + 3] * v.w + g_nac[16 + base + 3];
        ((float4*)out)[idx4] = r;
    }
}

// ---------------- launch ----------------
extern "C" void kernel_launch(void* const* d_in, const int* in_sizes, int n_in,
                              void* d_out, int out_size)
{
    const float* coords  = (const float*)d_in[0];
    const float* normals = (const float*)d_in[1];
    const float* curv    = (const float*)d_in[2];
    const void*  eidx    = d_in[3];
    const float* W1 = (const float*)d_in[4];
    const float* b1 = (const float*)d_in[5];
    const float* W2 = (const float*)d_in[6];
    const float* b2 = (const float*)d_in[7];
    const float* W3 = (const float*)d_in[8];
    const float* b3 = (const float*)d_in[9];
    const float* bn_e_gamma = (const float*)d_in[10];
    const float* bn_e_beta  = (const float*)d_in[11];
    const float* Wp = (const float*)d_in[12];
    const float* bp = (const float*)d_in[13];
    const float* bn_n_gamma = (const float*)d_in[14];
    const float* bn_n_beta  = (const float*)d_in[15];

    int N = in_sizes[0] / 3;
    long long E = (long long)(in_sizes[3] / 2);
    float* out = (float*)d_out;

    zero_kernel<<<(N * 16 + TPB - 1) / TPB, TPB>>>(N);                   // 0
    probe_kernel<<<1, 32>>>(eidx, N);                                     // 1
    pack_kernel<<<(N + TPB - 1) / TPB, TPB>>>(coords, normals, curv, N);  // 2
    edge_kernel<<<1184, ETPB>>>(eidx, E, W1, b1, W2, b2, W3, b3);         // 3 (ncu slot)
    sumS_kernel<<<256, 256>>>(N);                                         // 4
    fin_edge_kernel<<<1, 32>>>(bn_e_gamma, bn_e_beta, E);                 // 5
    node_kernel<<<(N + TPB - 1) / TPB, TPB>>>(Wp, bp, N);                 // 6
    fin_node_kernel<<<1, 32>>>(bn_n_gamma, bn_n_beta, N);                 // 7
    final_kernel<<<(N * 4 + TPB - 1) / TPB, TPB>>>(out, N);               // 8
}